// round 10
// baseline (speedup 1.0000x reference)
#include <cuda_runtime.h>
#include <cuda_fp16.h>
#include <cstdint>

#define B_DIM 4096
#define T_DIM 200
#define NEG_INF (-4294967295.0f)

// tiny smem layout (bytes)
#define OFF_QH   0       // f32 qh[32]
#define OFF_W2   128     // f32 w2[32]
#define OFF_SC   256     // f32 scores[200] (pad to 832)
#define OFF_RED  1088    // f32 red[16]
#define OFF_OP   1152    // u64 opart[8][32]
#define SMEM_BYTES 3200

__device__ float    g_wq[2048];    // W1a + W1c
__device__ uint32_t g_whi[1024];   // f16x2 fused weights, mma B-fragment order
__device__ uint32_t g_wlo[1024];   // f16 residuals

__global__ __launch_bounds__(256)
void setup_kernel(const float* __restrict__ W1)
{
    const int tid = threadIdx.x, blk = blockIdx.x;
    if (blk < 8) {
        const int i = blk * 256 + tid;
        g_wq[i] = W1[i] + W1[4096 + i];
        return;
    }
    const int idx = (blk - 8) * 256 + tid;
    int d2 = idx >> 5, j = idx & 31, k = 2 * d2;
    float w0 = W1[2048 + k * 32 + j] - W1[4096 + k * 32 + j];
    float w1 = W1[2048 + (k + 1) * 32 + j] - W1[4096 + (k + 1) * 32 + j];
    uint32_t hi, lo;
    asm("cvt.rn.f16x2.f32 %0, %1, %2;" : "=r"(hi) : "f"(w1), "f"(w0));
    float h0f = __half2float(__ushort_as_half((unsigned short)(hi & 0xFFFFu)));
    float h1f = __half2float(__ushort_as_half((unsigned short)(hi >> 16)));
    asm("cvt.rn.f16x2.f32 %0, %1, %2;" : "=r"(lo) : "f"(w1 - h1f), "f"(w0 - h0f));
    int ks = d2 >> 3, k2 = d2 & 7, t4 = k2 & 3, sel = k2 >> 2;
    int word = ((ks * 4 + t4) * 32 + j) * 2 + sel;
    g_whi[word] = hi;
    g_wlo[word] = lo;
}

static __device__ __forceinline__ float sigmoidf_fast(float h) {
    return __fdividef(1.0f, 1.0f + __expf(-h));
}

__global__ __launch_bounds__(256, 4)
void attn_pool_kernel(const float* __restrict__ query,
                      const float* __restrict__ keys,
                      const unsigned char* __restrict__ mask_raw,
                      const float* __restrict__ b1,
                      const float* __restrict__ W2,
                      const float* __restrict__ b2,
                      float* __restrict__ out)
{
    extern __shared__ char sm[];
    float* smf = (float*)sm;
    const int b    = blockIdx.x;
    const int tid  = threadIdx.x;
    const int lane = tid & 31;
    const int wid  = tid >> 5;
    const int g    = lane >> 2;
    const int t4   = lane & 3;
    uint32_t sbase;
    asm("{ .reg .u64 t; cvta.to.shared.u64 t, %1; cvt.u32.u64 %0, t; }"
        : "=r"(sbase) : "l"(sm));
    const float* kb = keys + (size_t)b * (T_DIM * 64);

    // ---- warp 0: qh chain (overlaps with other warps' GEMM) ----
    if (wid == 0) {
        float q0 = query[b * 64 + lane];
        float q1 = query[b * 64 + 32 + lane];
        float s = b1[lane];
        #pragma unroll
        for (int d = 0; d < 32; d++)
            s = fmaf(__shfl_sync(0xffffffffu, q0, d), g_wq[d * 32 + lane], s);
        #pragma unroll
        for (int d = 0; d < 32; d++)
            s = fmaf(__shfl_sync(0xffffffffu, q1, d), g_wq[(32 + d) * 32 + lane], s);
        smf[OFF_QH / 4 + lane] = s;
    }
    if (wid == 1) smf[OFF_W2 / 4 + lane] = __ldg(W2 + lane);

    // ---- mask dtype detect + per-thread mask bits + b2 ----
    int my_nz = 0;
    #pragma unroll
    for (int w = lane; w < 256; w += 32)
        my_nz |= mask_raw[4 * w + 1] | mask_raw[4 * w + 2] | mask_raw[4 * w + 3];
    const bool mode_u8 = __any_sync(0xffffffffu, my_nz != 0);
    const int* mask_i32 = (const int*)mask_raw;
    const float b2v = __ldg(b2);

    int mval = 0;
    if (t4 == 0) {
        #pragma unroll
        for (int mi = 0; mi < 2; mi++) {
            if (mi == 1 && wid >= 5) continue;
            const int m0 = (wid + 8 * mi) * 16;
            const int r0 = m0 + g, r1 = r0 + 8;
            bool v0 = mode_u8 ? (mask_raw[b * T_DIM + r0] != 0)
                              : (mask_i32[b * T_DIM + r0] != 0);
            mval |= (int)v0 << (2 * mi);
            if (r1 < T_DIM) {
                bool v1 = mode_u8 ? (mask_raw[b * T_DIM + r1] != 0)
                                  : (mask_i32[b * T_DIM + r1] != 0);
                mval |= (int)v1 << (2 * mi + 1);
            }
        }
    }

    // ====== score GEMM: A fragments straight from global keys (L2/L1) ======
    float acc[2][4][4];
    #pragma unroll
    for (int mi = 0; mi < 2; mi++)
        #pragma unroll
        for (int nt = 0; nt < 4; nt++)
            #pragma unroll
            for (int e = 0; e < 4; e++) acc[mi][nt][e] = 0.0f;

    const uint32_t wofs = (uint32_t)(t4 * 64 + g * 2);
    #pragma unroll
    for (int ks = 0; ks < 4; ks++) {
        uint2 bh[4], bl[4];
        #pragma unroll
        for (int nt = 0; nt < 4; nt++) {
            bh[nt] = __ldg((const uint2*)(g_whi + wofs + ks * 256 + nt * 16));
            bl[nt] = __ldg((const uint2*)(g_wlo + wofs + ks * 256 + nt * 16));
        }
        const int c0 = 16 * ks + (t4 >> 1) * 4 + (t4 & 1) * 2;   // k-col of a0
        #pragma unroll
        for (int mi = 0; mi < 2; mi++) {
            if (mi == 1 && wid >= 5) continue;
            const int m0 = (wid + 8 * mi) * 16;
            const float* arow = kb + (m0 + g) * 64 + c0;
            float2 A0 = __ldg((const float2*)(arow));
            float2 A2 = __ldg((const float2*)(arow + 8));
            uint32_t a0, a1, a2, a3;
            asm("cvt.rn.f16x2.f32 %0,%1,%2;" : "=r"(a0) : "f"(A0.y), "f"(A0.x));
            asm("cvt.rn.f16x2.f32 %0,%1,%2;" : "=r"(a2) : "f"(A2.y), "f"(A2.x));
            if ((m0 + g + 8) < T_DIM) {
                float2 A1 = __ldg((const float2*)(arow + 512));
                float2 A3 = __ldg((const float2*)(arow + 520));
                asm("cvt.rn.f16x2.f32 %0,%1,%2;" : "=r"(a1) : "f"(A1.y), "f"(A1.x));
                asm("cvt.rn.f16x2.f32 %0,%1,%2;" : "=r"(a3) : "f"(A3.y), "f"(A3.x));
            } else { a1 = 0u; a3 = 0u; }
            #pragma unroll
            for (int nt = 0; nt < 4; nt++) {
                asm volatile(
                    "mma.sync.aligned.m16n8k16.row.col.f32.f16.f16.f32 "
                    "{%0,%1,%2,%3}, {%4,%5,%6,%7}, {%8,%9}, {%0,%1,%2,%3};"
                    : "+f"(acc[mi][nt][0]), "+f"(acc[mi][nt][1]),
                      "+f"(acc[mi][nt][2]), "+f"(acc[mi][nt][3])
                    : "r"(a0), "r"(a1), "r"(a2), "r"(a3),
                      "r"(bh[nt].x), "r"(bh[nt].y));
                asm volatile(
                    "mma.sync.aligned.m16n8k16.row.col.f32.f16.f16.f32 "
                    "{%0,%1,%2,%3}, {%4,%5,%6,%7}, {%8,%9}, {%0,%1,%2,%3};"
                    : "+f"(acc[mi][nt][0]), "+f"(acc[mi][nt][1]),
                      "+f"(acc[mi][nt][2]), "+f"(acc[mi][nt][3])
                    : "r"(a0), "r"(a1), "r"(a2), "r"(a3),
                      "r"(bl[nt].x), "r"(bl[nt].y));
            }
        }
    }
    __syncthreads();   // qh/w2 visible; all scores-smem writers aligned

    // ---- epilogue: h = C + qh ; sigmoid; dot W2; reduce over t4; mask ----
    #pragma unroll
    for (int mi = 0; mi < 2; mi++) {
        if (mi == 1 && wid >= 5) continue;
        const int m0 = (wid + 8 * mi) * 16;
        float s_lo = 0.0f, s_hi = 0.0f;
        #pragma unroll
        for (int nt = 0; nt < 4; nt++) {
            const int j0 = 8 * nt + 2 * t4;
            float2 qh2 = *(float2*)(sm + OFF_QH + j0 * 4);
            float2 w22 = *(float2*)(sm + OFF_W2 + j0 * 4);
            s_lo = fmaf(sigmoidf_fast(acc[mi][nt][0] + qh2.x), w22.x, s_lo);
            s_lo = fmaf(sigmoidf_fast(acc[mi][nt][1] + qh2.y), w22.y, s_lo);
            s_hi = fmaf(sigmoidf_fast(acc[mi][nt][2] + qh2.x), w22.x, s_hi);
            s_hi = fmaf(sigmoidf_fast(acc[mi][nt][3] + qh2.y), w22.y, s_hi);
        }
        s_lo += __shfl_xor_sync(0xffffffffu, s_lo, 1);
        s_lo += __shfl_xor_sync(0xffffffffu, s_lo, 2);
        s_hi += __shfl_xor_sync(0xffffffffu, s_hi, 1);
        s_hi += __shfl_xor_sync(0xffffffffu, s_hi, 2);
        if (t4 == 0) {
            const int r0 = m0 + g, r1 = r0 + 8;
            smf[OFF_SC / 4 + r0] = ((mval >> (2 * mi)) & 1) ? (s_lo + b2v) : NEG_INF;
            if (r1 < T_DIM)
                smf[OFF_SC / 4 + r1] = ((mval >> (2 * mi + 1)) & 1) ? (s_hi + b2v) : NEG_INF;
        }
    }
    __syncthreads();

    // ---- parallel softmax: warp w owns scores [25w, 25w+25) ----
    const int t0 = wid * 25;
    {
        float m = -1e38f;
        if (lane < 25) m = smf[OFF_SC / 4 + t0 + lane];
        #pragma unroll
        for (int o = 16; o; o >>= 1) m = fmaxf(m, __shfl_xor_sync(0xffffffffu, m, o));
        if (lane == 0) smf[OFF_RED / 4 + wid] = m;
    }
    __syncthreads();
    float sinv;
    {
        float gm = smf[OFF_RED / 4];
        #pragma unroll
        for (int p = 1; p < 8; p++) gm = fmaxf(gm, smf[OFF_RED / 4 + p]);
        float e = 0.0f;
        if (lane < 25) {
            e = __expf(smf[OFF_SC / 4 + t0 + lane] - gm);
            smf[OFF_SC / 4 + t0 + lane] = e;
        }
        float s = e;
        #pragma unroll
        for (int o = 16; o; o >>= 1) s += __shfl_xor_sync(0xffffffffu, s, o);
        if (lane == 0) smf[OFF_RED / 4 + 8 + wid] = s;
        __syncthreads();
        float gs = smf[OFF_RED / 4 + 8];
        #pragma unroll
        for (int p = 1; p < 8; p++) gs += smf[OFF_RED / 4 + 8 + p];
        sinv = __fdividef(1.0f, gs);
    }

    // ---- weighted key sum from global keys (L1-resident), f32x2 over d-pairs ----
    {
        unsigned long long acw = 0ull;
        #pragma unroll 5
        for (int t = t0; t < t0 + 25; t++) {
            float p = smf[OFF_SC / 4 + t];
            unsigned long long pd;
            asm("mov.b64 %0,{%1,%1};" : "=l"(pd) : "r"(__float_as_uint(p)));
            unsigned long long kv;
            asm("ld.global.nc.b64 %0,[%1];" : "=l"(kv) : "l"(kb + t * 64 + lane * 2));
            asm("fma.rn.f32x2 %0,%1,%2,%0;" : "+l"(acw) : "l"(kv), "l"(pd));
        }
        unsigned long long sd;
        asm("mov.b64 %0,{%1,%1};" : "=l"(sd) : "r"(__float_as_uint(sinv)));
        unsigned long long zero = 0ull, scaled;
        asm("fma.rn.f32x2 %0,%1,%2,%3;" : "=l"(scaled) : "l"(acw), "l"(sd), "l"(zero));
        asm volatile("st.shared.b64 [%0],%1;"
                     :: "r"(sbase + OFF_OP + wid * 256 + lane * 8), "l"(scaled));
    }
    __syncthreads();
    if (tid < 64) {
        float r = 0.0f;
        #pragma unroll
        for (int p = 0; p < 8; p++)
            r += smf[(OFF_OP + p * 256) / 4 + tid];
        out[b * 64 + tid] = r;
    }
}

extern "C" void kernel_launch(void* const* d_in, const int* in_sizes, int n_in,
                              void* d_out, int out_size)
{
    const float*         query = (const float*)d_in[0];
    const float*         keys  = (const float*)d_in[1];
    const unsigned char* mask  = (const unsigned char*)d_in[2];
    const float*         W1    = (const float*)d_in[3];
    const float*         b1    = (const float*)d_in[4];
    const float*         W2    = (const float*)d_in[5];
    const float*         b2    = (const float*)d_in[6];
    float* out = (float*)d_out;

    setup_kernel<<<12, 256>>>(W1);
    cudaFuncSetAttribute(attn_pool_kernel,
                         cudaFuncAttributeMaxDynamicSharedMemorySize, SMEM_BYTES);
    attn_pool_kernel<<<B_DIM, 256, SMEM_BYTES>>>(query, keys, mask, b1, W2, b2, out);
}

// round 11
// speedup vs baseline: 1.3593x; 1.3593x over previous
#include <cuda_runtime.h>
#include <cuda_fp16.h>
#include <cstdint>

#define B_DIM 4096
#define T_DIM 200
#define NEG_INF (-4294967295.0f)
#define KROW 144          // f16 key row stride in bytes (36 words; 36 mod 32 = 4)

// smem byte offsets
#define OFF_K    0        // f16 keys, 200 x KROW
#define OFF_WT   28800    // staged weight tables: hi[1152 w] + lo[1152 w] = 9216 B
#define OFF_QH   38016    // f32 qh[32]
#define OFF_W2   38144    // f32 w2[32]
#define OFF_SC   38272    // f32 scores[200] (pad 832)
#define OFF_RED  39104    // f32 red[16]
#define OFF_OP   39168    // float2 opart[8][32]
#define SMEM_BYTES 41216

__device__ float    g_wq[2048];    // W1a + W1c
__device__ uint32_t g_wtab[2304];  // [0,1152): f16x2 hi fragments; [1152,2304): lo

__global__ __launch_bounds__(256)
void setup_kernel(const float* __restrict__ W1)
{
    const int tid = threadIdx.x, blk = blockIdx.x;
    if (blk < 8) {
        const int i = blk * 256 + tid;
        g_wq[i] = W1[i] + W1[4096 + i];
        return;
    }
    const int idx = (blk - 8) * 256 + tid;        // 0..1023
    int d2 = idx >> 5, j = idx & 31, k = 2 * d2;
    float w0 = W1[2048 + k * 32 + j] - W1[4096 + k * 32 + j];
    float w1 = W1[2048 + (k + 1) * 32 + j] - W1[4096 + (k + 1) * 32 + j];
    uint32_t hi, lo;
    asm("cvt.rn.f16x2.f32 %0, %1, %2;" : "=r"(hi) : "f"(w1), "f"(w0));
    float h0f = __half2float(__ushort_as_half((unsigned short)(hi & 0xFFFFu)));
    float h1f = __half2float(__ushort_as_half((unsigned short)(hi >> 16)));
    asm("cvt.rn.f16x2.f32 %0, %1, %2;" : "=r"(lo) : "f"(w1 - h1f), "f"(w0 - h0f));
    int ks = d2 >> 3, k2 = d2 & 7, t4 = k2 & 3, sel = k2 >> 2;
    // padded fragment layout: t4 stride 72 words (288 B), ks stride 288 words
    int word = ks * 288 + t4 * 72 + j * 2 + sel;
    g_wtab[word]        = hi;
    g_wtab[1152 + word] = lo;
}

static __device__ __forceinline__ float sigmoidf_fast(float h) {
    return __fdividef(1.0f, 1.0f + __expf(-h));
}

__global__ __launch_bounds__(256, 4)
void attn_pool_kernel(const float* __restrict__ query,
                      const float* __restrict__ keys,
                      const unsigned char* __restrict__ mask_raw,
                      const float* __restrict__ b1,
                      const float* __restrict__ W2,
                      const float* __restrict__ b2,
                      float* __restrict__ out)
{
    extern __shared__ char sm[];
    float* smf = (float*)sm;
    const int b    = blockIdx.x;
    const int tid  = threadIdx.x;
    const int lane = tid & 31;
    const int wid  = tid >> 5;
    const int g    = lane >> 2;
    const int t4   = lane & 3;
    uint32_t sbase;
    asm("{ .reg .u64 t; cvta.to.shared.u64 t, %1; cvt.u32.u64 %0, t; }"
        : "=r"(sbase) : "l"(sm));
    const float* kb = keys + (size_t)b * (T_DIM * 64);

    // ---- stage weight tables via cp.async (from L2) ----
    for (int i = tid; i < 576; i += 256)
        asm volatile("cp.async.cg.shared.global [%0], [%1], 16;"
                     :: "r"(sbase + OFF_WT + i * 16), "l"((const char*)g_wtab + i * 16));
    asm volatile("cp.async.commit_group;" ::: "memory");

    // ---- stage keys: fp32 LDG.128 -> f16x2 -> STS.64, padded rows ----
    #pragma unroll 4
    for (int i = tid; i < T_DIM * 16; i += 256) {
        int r = i >> 4, c = i & 15;
        float4 v = __ldg((const float4*)kb + i);
        uint32_t p0, p1;
        asm("cvt.rn.f16x2.f32 %0,%1,%2;" : "=r"(p0) : "f"(v.y), "f"(v.x));
        asm("cvt.rn.f16x2.f32 %0,%1,%2;" : "=r"(p1) : "f"(v.w), "f"(v.z));
        asm volatile("st.shared.v2.b32 [%0],{%1,%2};"
                     :: "r"(sbase + OFF_K + r * KROW + c * 8), "r"(p0), "r"(p1));
    }

    // ---- warp 0: qh chain ; warp 1: w2 ----
    if (wid == 0) {
        float q0 = query[b * 64 + lane];
        float q1 = query[b * 64 + 32 + lane];
        float s = b1[lane];
        #pragma unroll
        for (int d = 0; d < 32; d++)
            s = fmaf(__shfl_sync(0xffffffffu, q0, d), g_wq[d * 32 + lane], s);
        #pragma unroll
        for (int d = 0; d < 32; d++)
            s = fmaf(__shfl_sync(0xffffffffu, q1, d), g_wq[(32 + d) * 32 + lane], s);
        smf[OFF_QH / 4 + lane] = s;
    }
    if (wid == 1) smf[OFF_W2 / 4 + lane] = __ldg(W2 + lane);

    // ---- mask dtype detect + per-thread mask bits + b2 ----
    int my_nz = 0;
    #pragma unroll
    for (int w = lane; w < 256; w += 32)
        my_nz |= mask_raw[4 * w + 1] | mask_raw[4 * w + 2] | mask_raw[4 * w + 3];
    const bool mode_u8 = __any_sync(0xffffffffu, my_nz != 0);
    const int* mask_i32 = (const int*)mask_raw;
    const float b2v = __ldg(b2);

    int mval = 0;
    if (t4 == 0) {
        #pragma unroll
        for (int mi = 0; mi < 2; mi++) {
            if (mi == 1 && wid >= 5) continue;
            const int m0 = (wid + 8 * mi) * 16;
            const int r0 = m0 + g, r1 = r0 + 8;
            bool v0 = mode_u8 ? (mask_raw[b * T_DIM + r0] != 0)
                              : (mask_i32[b * T_DIM + r0] != 0);
            mval |= (int)v0 << (2 * mi);
            if (r1 < T_DIM) {
                bool v1 = mode_u8 ? (mask_raw[b * T_DIM + r1] != 0)
                                  : (mask_i32[b * T_DIM + r1] != 0);
                mval |= (int)v1 << (2 * mi + 1);
            }
        }
    }

    asm volatile("cp.async.wait_group 0;" ::: "memory");
    __syncthreads();

    // ====== score GEMM: m16n8k16 f16; A = f16 keys (smem), B = smem tables ======
    float acc[2][4][4];
    #pragma unroll
    for (int mi = 0; mi < 2; mi++)
        #pragma unroll
        for (int nt = 0; nt < 4; nt++)
            #pragma unroll
            for (int e = 0; e < 4; e++) acc[mi][nt][e] = 0.0f;

    #pragma unroll
    for (int ks = 0; ks < 4; ks++) {
        const uint32_t wrow = sbase + OFF_WT + (uint32_t)(ks * 1152 + t4 * 288 + g * 8);
        uint2 bh[4], bl[4];
        #pragma unroll
        for (int nt = 0; nt < 4; nt++) {
            asm("ld.shared.v2.u32 {%0,%1},[%2];"
                : "=r"(bh[nt].x), "=r"(bh[nt].y) : "r"(wrow + nt * 64));
            asm("ld.shared.v2.u32 {%0,%1},[%2];"
                : "=r"(bl[nt].x), "=r"(bl[nt].y) : "r"(wrow + nt * 64 + 4608));
        }
        #pragma unroll
        for (int mi = 0; mi < 2; mi++) {
            if (mi == 1 && wid >= 5) continue;
            const int m0 = (wid + 8 * mi) * 16;
            const uint32_t abase = sbase + OFF_K +
                                   (uint32_t)((m0 + g) * KROW + ks * 32 + t4 * 4);
            uint32_t a0, a1, a2, a3;
            asm("ld.shared.b32 %0,[%1];" : "=r"(a0) : "r"(abase));
            asm("ld.shared.b32 %0,[%1];" : "=r"(a2) : "r"(abase + 16));
            if ((m0 + g + 8) < T_DIM) {
                asm("ld.shared.b32 %0,[%1];" : "=r"(a1) : "r"(abase + 8 * KROW));
                asm("ld.shared.b32 %0,[%1];" : "=r"(a3) : "r"(abase + 8 * KROW + 16));
            } else { a1 = 0u; a3 = 0u; }
            #pragma unroll
            for (int nt = 0; nt < 4; nt++) {
                asm volatile(
                    "mma.sync.aligned.m16n8k16.row.col.f32.f16.f16.f32 "
                    "{%0,%1,%2,%3}, {%4,%5,%6,%7}, {%8,%9}, {%0,%1,%2,%3};"
                    : "+f"(acc[mi][nt][0]), "+f"(acc[mi][nt][1]),
                      "+f"(acc[mi][nt][2]), "+f"(acc[mi][nt][3])
                    : "r"(a0), "r"(a1), "r"(a2), "r"(a3),
                      "r"(bh[nt].x), "r"(bh[nt].y));
                asm volatile(
                    "mma.sync.aligned.m16n8k16.row.col.f32.f16.f16.f32 "
                    "{%0,%1,%2,%3}, {%4,%5,%6,%7}, {%8,%9}, {%0,%1,%2,%3};"
                    : "+f"(acc[mi][nt][0]), "+f"(acc[mi][nt][1]),
                      "+f"(acc[mi][nt][2]), "+f"(acc[mi][nt][3])
                    : "r"(a0), "r"(a1), "r"(a2), "r"(a3),
                      "r"(bl[nt].x), "r"(bl[nt].y));
            }
        }
    }

    // ---- epilogue: h = C + qh ; sigmoid; dot W2; reduce over t4; mask ----
    #pragma unroll
    for (int mi = 0; mi < 2; mi++) {
        if (mi == 1 && wid >= 5) continue;
        const int m0 = (wid + 8 * mi) * 16;
        float s_lo = 0.0f, s_hi = 0.0f;
        #pragma unroll
        for (int nt = 0; nt < 4; nt++) {
            const int j0 = 8 * nt + 2 * t4;
            float2 qh2 = *(float2*)(sm + OFF_QH + j0 * 4);
            float2 w22 = *(float2*)(sm + OFF_W2 + j0 * 4);
            s_lo = fmaf(sigmoidf_fast(acc[mi][nt][0] + qh2.x), w22.x, s_lo);
            s_lo = fmaf(sigmoidf_fast(acc[mi][nt][1] + qh2.y), w22.y, s_lo);
            s_hi = fmaf(sigmoidf_fast(acc[mi][nt][2] + qh2.x), w22.x, s_hi);
            s_hi = fmaf(sigmoidf_fast(acc[mi][nt][3] + qh2.y), w22.y, s_hi);
        }
        s_lo += __shfl_xor_sync(0xffffffffu, s_lo, 1);
        s_lo += __shfl_xor_sync(0xffffffffu, s_lo, 2);
        s_hi += __shfl_xor_sync(0xffffffffu, s_hi, 1);
        s_hi += __shfl_xor_sync(0xffffffffu, s_hi, 2);
        if (t4 == 0) {
            const int r0 = m0 + g, r1 = r0 + 8;
            smf[OFF_SC / 4 + r0] = ((mval >> (2 * mi)) & 1) ? (s_lo + b2v) : NEG_INF;
            if (r1 < T_DIM)
                smf[OFF_SC / 4 + r1] = ((mval >> (2 * mi + 1)) & 1) ? (s_hi + b2v) : NEG_INF;
        }
    }
    __syncthreads();

    // ---- parallel softmax: warp w owns scores [25w, 25w+25) ----
    const int t0 = wid * 25;
    {
        float m = -1e38f;
        if (lane < 25) m = smf[OFF_SC / 4 + t0 + lane];
        #pragma unroll
        for (int o = 16; o; o >>= 1) m = fmaxf(m, __shfl_xor_sync(0xffffffffu, m, o));
        if (lane == 0) smf[OFF_RED / 4 + wid] = m;
    }
    __syncthreads();
    float sinv;
    {
        float gm = smf[OFF_RED / 4];
        #pragma unroll
        for (int p = 1; p < 8; p++) gm = fmaxf(gm, smf[OFF_RED / 4 + p]);
        float e = 0.0f;
        if (lane < 25) {
            e = __expf(smf[OFF_SC / 4 + t0 + lane] - gm);
            smf[OFF_SC / 4 + t0 + lane] = e;
        }
        float s = e;
        #pragma unroll
        for (int o = 16; o; o >>= 1) s += __shfl_xor_sync(0xffffffffu, s, o);
        if (lane == 0) smf[OFF_RED / 4 + 8 + wid] = s;
        __syncthreads();
        float gs = smf[OFF_RED / 4 + 8];
        #pragma unroll
        for (int p = 1; p < 8; p++) gs += smf[OFF_RED / 4 + 8 + p];
        sinv = __fdividef(1.0f, gs);
    }

    // ---- weighted key sum from f16 smem keys; lane owns d-pair (2lane, 2lane+1) ----
    {
        float ax = 0.0f, ay = 0.0f;
        #pragma unroll 5
        for (int t = t0; t < t0 + 25; t++) {
            float p = smf[OFF_SC / 4 + t];
            uint32_t kv;
            asm("ld.shared.b32 %0,[%1];" : "=r"(kv)
                : "r"(sbase + OFF_K + t * KROW + lane * 4));
            float kx, ky;
            asm("{ .reg .b16 l, h; mov.b32 {l,h}, %2; cvt.f32.f16 %0, l; cvt.f32.f16 %1, h; }"
                : "=f"(kx), "=f"(ky) : "r"(kv));
            ax = fmaf(p, kx, ax);
            ay = fmaf(p, ky, ay);
        }
        float2 sc2 = make_float2(ax * sinv, ay * sinv);
        *(float2*)(sm + OFF_OP + wid * 256 + lane * 8) = sc2;
    }
    __syncthreads();
    if (tid < 64) {
        float r = 0.0f;
        #pragma unroll
        for (int p = 0; p < 8; p++)
            r += smf[(OFF_OP + p * 256) / 4 + tid];
        out[b * 64 + tid] = r;
    }
}

extern "C" void kernel_launch(void* const* d_in, const int* in_sizes, int n_in,
                              void* d_out, int out_size)
{
    const float*         query = (const float*)d_in[0];
    const float*         keys  = (const float*)d_in[1];
    const unsigned char* mask  = (const unsigned char*)d_in[2];
    const float*         W1    = (const float*)d_in[3];
    const float*         b1    = (const float*)d_in[4];
    const float*         W2    = (const float*)d_in[5];
    const float*         b2    = (const float*)d_in[6];
    float* out = (float*)d_out;

    setup_kernel<<<12, 256>>>(W1);
    cudaFuncSetAttribute(attn_pool_kernel,
                         cudaFuncAttributeMaxDynamicSharedMemorySize, SMEM_BYTES);
    attn_pool_kernel<<<B_DIM, 256, SMEM_BYTES>>>(query, keys, mask, b1, W2, b2, out);
}